// round 2
// baseline (speedup 1.0000x reference)
#include <cuda_runtime.h>
#include <cstdint>

#define MAXN 50048
#define MAXE 800000
#define F    128   // in = out feats
#define F4   32    // float4s per row

// Scratch (device globals: no allocation allowed)
__device__ float g_h[(size_t)MAXN * F];   // aggregated features
__device__ int   g_dout[MAXN];
__device__ int   g_din[MAXN];
__device__ float g_iso[MAXN];             // deg_out^{-1/2}
__device__ float g_isi[MAXN];             // deg_in^{-1/2}
__device__ int   g_rowstart[MAXN + 1];    // CSR-by-dst row offsets
__device__ int   g_cursor[MAXN];          // fill cursors (init = rowstart)
__device__ int   g_esrc[MAXE];            // src index per edge, grouped by dst

// ---------------------------------------------------------------------------
// K0: zero degree counters only (h is fully written by gather; no memset)
// ---------------------------------------------------------------------------
__global__ void k_zero(int n) {
    int i = blockIdx.x * blockDim.x + threadIdx.x;
    if (i < n) { g_dout[i] = 0; g_din[i] = 0; }
}

// ---------------------------------------------------------------------------
// K1: degree histograms
// ---------------------------------------------------------------------------
__global__ void k_deg(const int* __restrict__ src, const int* __restrict__ dst, int E) {
    int i = blockIdx.x * blockDim.x + threadIdx.x;
    int stride = gridDim.x * blockDim.x;
    for (int e = i; e < E; e += stride) {
        atomicAdd(&g_dout[src[e]], 1);
        atomicAdd(&g_din[dst[e]], 1);
    }
}

// ---------------------------------------------------------------------------
// K2: single-block exclusive scan of din -> rowstart (+cursor copy),
//     fused with inverse-sqrt degree computation.
// Per-thread contiguous chunk + one Kogge-Stone block scan of 1024 partials.
// ---------------------------------------------------------------------------
__global__ void k_scan(int n) {
    __shared__ int sums[1024];
    int t = threadIdx.x;
    int C = (n + 1023) >> 10;            // elements per thread
    int b0 = t * C;
    int b1 = b0 + C; if (b1 > n) b1 = n;

    int s = 0;
    for (int i = b0; i < b1; i++) s += g_din[i];
    sums[t] = s;
    __syncthreads();

    #pragma unroll
    for (int off = 1; off < 1024; off <<= 1) {
        int v = (t >= off) ? sums[t - off] : 0;
        __syncthreads();
        sums[t] += v;
        __syncthreads();
    }

    int run = sums[t] - s;               // exclusive prefix for this chunk
    for (int i = b0; i < b1; i++) {
        g_rowstart[i] = run;
        g_cursor[i]   = run;
        run += g_din[i];
    }
    if (t == 1023) g_rowstart[n] = sums[1023];

    // fused: inverse sqrt degrees (clamped to >= 1)
    for (int i = t; i < n; i += 1024) {
        int dOut = g_dout[i]; if (dOut < 1) dOut = 1;
        int dIn  = g_din[i];  if (dIn  < 1) dIn  = 1;
        g_iso[i] = rsqrtf((float)dOut);
        g_isi[i] = rsqrtf((float)dIn);
    }
}

// ---------------------------------------------------------------------------
// K3: bucket-fill edge src indices grouped by dst
// ---------------------------------------------------------------------------
__global__ void k_fill(const int* __restrict__ src, const int* __restrict__ dst, int E) {
    int i = blockIdx.x * blockDim.x + threadIdx.x;
    if (i < E) {
        int d = dst[i];
        int pos = atomicAdd(&g_cursor[d], 1);
        g_esrc[pos] = src[i];
    }
}

// ---------------------------------------------------------------------------
// K4: gather  h[v] = sum over in-edges of x[src]*iso[src]
// One warp per dst row. Lanes cooperatively fetch up to 32 edge indices +
// scales (coalesced), broadcast each via shfl; each lane owns one float4
// chunk of the 128-float row. Full chunks fully unrolled for MLP.
// ---------------------------------------------------------------------------
__global__ void k_gather(const float* __restrict__ x, int n) {
    int gtid = blockIdx.x * blockDim.x + threadIdx.x;
    int v    = gtid >> 5;
    int lane = gtid & 31;
    if (v >= n) return;

    int start = g_rowstart[v];
    int end   = g_rowstart[v + 1];
    const float4* x4 = reinterpret_cast<const float4*>(x);

    float4 acc = make_float4(0.f, 0.f, 0.f, 0.f);

    for (int base = start; base < end; base += 32) {
        int idx = base + lane;
        int   myS  = 0;
        float mySc = 0.f;
        if (idx < end) { myS = g_esrc[idx]; mySc = g_iso[myS]; }
        int cnt = end - base; if (cnt > 32) cnt = 32;

        if (cnt == 32) {
            #pragma unroll
            for (int k = 0; k < 32; k++) {
                int   s  = __shfl_sync(0xffffffffu, myS,  k);
                float sc = __shfl_sync(0xffffffffu, mySc, k);
                float4 xv = x4[(size_t)s * F4 + lane];
                acc.x = fmaf(xv.x, sc, acc.x);
                acc.y = fmaf(xv.y, sc, acc.y);
                acc.z = fmaf(xv.z, sc, acc.z);
                acc.w = fmaf(xv.w, sc, acc.w);
            }
        } else {
            #pragma unroll 4
            for (int k = 0; k < cnt; k++) {
                int   s  = __shfl_sync(0xffffffffu, myS,  k);
                float sc = __shfl_sync(0xffffffffu, mySc, k);
                float4 xv = x4[(size_t)s * F4 + lane];
                acc.x = fmaf(xv.x, sc, acc.x);
                acc.y = fmaf(xv.y, sc, acc.y);
                acc.z = fmaf(xv.z, sc, acc.z);
                acc.w = fmaf(xv.w, sc, acc.w);
            }
        }
    }

    reinterpret_cast<float4*>(g_h)[(size_t)v * F4 + lane] = acc;
}

// ---------------------------------------------------------------------------
// K5: out = (h @ W) * isi[row] + bias
// 64 rows x 128 cols per block, K-tiles of 32, packed fma.rn.f32x2.
// ---------------------------------------------------------------------------
__global__ void k_gemm(const float* __restrict__ W,
                       const float* __restrict__ bias,
                       float* __restrict__ out, int n) {
    __shared__ float Ws[32][F];     // [kk][col]   16 KB
    __shared__ float Hs[64][32];    // [row][kk]    8 KB

    int tid  = threadIdx.x;          // 0..255
    int tcol = tid & 31;             // col4 index
    int trow = tid >> 5;             // 0..7 -> rows trow*8 .. trow*8+7
    int row0 = blockIdx.x * 64;

    unsigned long long acc2[8][2];
    #pragma unroll
    for (int r = 0; r < 8; r++) { acc2[r][0] = 0ull; acc2[r][1] = 0ull; }

    const float4* h4 = reinterpret_cast<const float4*>(g_h);

    for (int kt = 0; kt < 4; kt++) {
        int k0 = kt * 32;
        #pragma unroll
        for (int i = tid; i < 1024; i += 256) {
            int wr = i >> 5;
            int wc = i & 31;
            float4 wv = reinterpret_cast<const float4*>(W)[(size_t)(k0 + wr) * F4 + wc];
            *reinterpret_cast<float4*>(&Ws[wr][wc << 2]) = wv;
        }
        #pragma unroll
        for (int i = tid; i < 512; i += 256) {
            int hr = i >> 3;
            int hc = i & 7;
            int gr = row0 + hr;
            float4 hv = make_float4(0.f, 0.f, 0.f, 0.f);
            if (gr < n) hv = h4[(size_t)gr * F4 + (k0 >> 2) + hc];
            *reinterpret_cast<float4*>(&Hs[hr][hc << 2]) = hv;
        }
        __syncthreads();

        #pragma unroll
        for (int kk = 0; kk < 32; kk++) {
            float4 wv = *reinterpret_cast<const float4*>(&Ws[kk][tcol << 2]);
            unsigned long long wlo, whi;
            asm("mov.b64 %0, {%1,%2};" : "=l"(wlo) : "f"(wv.x), "f"(wv.y));
            asm("mov.b64 %0, {%1,%2};" : "=l"(whi) : "f"(wv.z), "f"(wv.w));
            #pragma unroll
            for (int r = 0; r < 8; r++) {
                float hv = Hs[trow * 8 + r][kk];
                unsigned long long hh;
                asm("mov.b64 %0, {%1,%1};" : "=l"(hh) : "f"(hv));
                asm("fma.rn.f32x2 %0, %1, %2, %0;"
                    : "+l"(acc2[r][0]) : "l"(hh), "l"(wlo));
                asm("fma.rn.f32x2 %0, %1, %2, %0;"
                    : "+l"(acc2[r][1]) : "l"(hh), "l"(whi));
            }
        }
        __syncthreads();
    }

    float4 bv = reinterpret_cast<const float4*>(bias)[tcol];
    #pragma unroll
    for (int r = 0; r < 8; r++) {
        int row = row0 + trow * 8 + r;
        if (row < n) {
            float s = g_isi[row];
            float ax, ay, az, aw;
            asm("mov.b64 {%0,%1}, %2;" : "=f"(ax), "=f"(ay) : "l"(acc2[r][0]));
            asm("mov.b64 {%0,%1}, %2;" : "=f"(az), "=f"(aw) : "l"(acc2[r][1]));
            float4 o;
            o.x = ax * s + bv.x;
            o.y = ay * s + bv.y;
            o.z = az * s + bv.z;
            o.w = aw * s + bv.w;
            reinterpret_cast<float4*>(out)[(size_t)row * F4 + tcol] = o;
        }
    }
}

// ---------------------------------------------------------------------------
extern "C" void kernel_launch(void* const* d_in, const int* in_sizes, int n_in,
                              void* d_out, int out_size) {
    const float* x    = (const float*)d_in[0];
    const int*   src  = (const int*)d_in[1];
    const int*   dst  = (const int*)d_in[2];
    const float* W    = (const float*)d_in[3];
    const float* bias = (const float*)d_in[4];
    float*       out  = (float*)d_out;

    int n = in_sizes[0] / F;   // 50000
    int E = in_sizes[1];       // 800000

    k_zero<<<(n + 255) / 256, 256>>>(n);
    k_deg<<<(E + 255) / 256, 256>>>(src, dst, E);
    k_scan<<<1, 1024>>>(n);
    k_fill<<<(E + 255) / 256, 256>>>(src, dst, E);
    k_gather<<<(n * 32 + 255) / 256, 256>>>(x, n);
    k_gemm<<<(n + 63) / 64, 256>>>(W, bias, out, n);
}